// round 16
// baseline (speedup 1.0000x reference)
#include <cuda_runtime.h>
#include <cuda_fp16.h>
#include <cstdint>

// ---------------------------------------------------------------- shapes
#define BB   64
#define NN   64
#define DD   24
#define HH   256
#define EPN  63
#define ETOT 4032
#define GRID 148
#define NTILE 2048

// ---------------------------------------------------------------- scratch
__device__ float g_X  [BB*NN*DD];
__device__ float g_Hs [2][BB*NN*HH];
__device__ float g_Hr [2][BB*NN*HH];
__device__ float g_agg2[2][BB*NN*HH];              // per-k partial aggregation
__device__ float g_Q  [BB*NN];
__device__ __align__(16) __half g_w2t[2][HH*HH];   // fp16(W2^T): [k][n][kk]
__device__ __align__(16) __half g_w1t[256*288];    // fp16(Wo1^T)
__device__ __align__(16) __half g_w2o[256*256];    // fp16(Wo2^T)

// ---------------------------------------------------------------- helpers
__device__ __forceinline__ void mma16816(float* c, const uint32_t* a, const uint32_t* b) {
    asm volatile(
        "mma.sync.aligned.m16n8k16.row.col.f32.f16.f16.f32 "
        "{%0,%1,%2,%3}, {%4,%5,%6,%7}, {%8,%9}, {%0,%1,%2,%3};\n"
        : "+f"(c[0]), "+f"(c[1]), "+f"(c[2]), "+f"(c[3])
        : "r"(a[0]), "r"(a[1]), "r"(a[2]), "r"(a[3]), "r"(b[0]), "r"(b[1]));
}
#define LDM_X4(r, addr) \
    asm volatile("ldmatrix.sync.aligned.m8n8.x4.shared.b16 {%0,%1,%2,%3}, [%4];" \
        : "=r"((r)[0]), "=r"((r)[1]), "=r"((r)[2]), "=r"((r)[3]) : "r"(addr))

__device__ __forceinline__ void cp16(uint32_t dst, const void* src) {
    asm volatile("cp.async.cg.shared.global [%0], [%1], 16;\n" :: "r"(dst), "l"(src) : "memory");
}
#define CP_COMMIT() asm volatile("cp.async.commit_group;\n" ::: "memory")
#define CP_WAIT(n)  asm volatile("cp.async.wait_group %0;\n" :: "n"(n) : "memory")

__device__ __forceinline__ uint32_t smem_u32(const void* p) {
    uint32_t a;
    asm("{ .reg .u64 t; cvta.to.shared.u64 t, %1; cvt.u32.u64 %0, t; }" : "=r"(a) : "l"(p));
    return a;
}
__device__ __forceinline__ uint32_t pack_h2(float x, float y) {
    __half hx = __float2half_rn(x), hy = __float2half_rn(y);
    return ((uint32_t)__half_as_ushort(hy) << 16) | __half_as_ushort(hx);
}

// ---------------------------------------------------------------- weight prep
__global__ __launch_bounds__(256) void wprep_kernel(const float* __restrict__ W2) {
    int k  = blockIdx.x >> 8;
    int c  = blockIdx.x & 255;
    int kk = threadIdx.x;
    g_w2t[k][c*HH + kk] = __float2half_rn(W2[(k*HH + kk)*HH + c]);
}
__global__ __launch_bounds__(256) void oprep_kernel(const float* __restrict__ Wo1,
                                                    const float* __restrict__ Wo2) {
    int n = blockIdx.x;
    int t = threadIdx.x;
    for (int kk = t; kk < 288; kk += 256)
        g_w1t[n*288 + kk] = (kk < 280) ? __float2half_rn(Wo1[kk*256 + n]) : __half(0.f);
    g_w2o[n*256 + t] = __float2half_rn(Wo2[t*256 + n]);
}

// ---------------------------------------------------------------- node projections
__global__ __launch_bounds__(256) void nodeproj_kernel(
    const float* __restrict__ data, const float* __restrict__ act,
    const float* __restrict__ W1, const float* __restrict__ b1)
{
    int bn = blockIdx.x;
    int h  = threadIdx.x;
    __shared__ float xs[DD];
    if (h < 16)      xs[h] = data[bn*32 + h];
    else if (h < 24) xs[h] = act [bn*16 + (h-16)];
    __syncthreads();
    if (h < DD) g_X[bn*DD + h] = xs[h];

    float xr[DD];
#pragma unroll
    for (int d = 0; d < DD; d++) xr[d] = xs[d];
#pragma unroll
    for (int k = 0; k < 2; k++) {
        float hs = 0.f, hr = b1[k*HH + h];
#pragma unroll
        for (int d = 0; d < DD; d++) {
            hs = fmaf(xr[d], W1[(k*48 +      d)*HH + h], hs);
            hr = fmaf(xr[d], W1[(k*48 + 24 + d)*HH + h], hr);
        }
        g_Hs[k][bn*HH + h] = hs;
        g_Hr[k][bn*HH + h] = hr;
    }
}

// ---------------------------------------------------------------- edge GEMM (persistent)
// grid=148, 512 threads (16 warps: wm=wid&3 rows, wn=wid>>2 cols).
// For each k: W2^T resident in SMEM once; loop over (b,pair) tiles: M=128,N=256,K=256.
// Mainloop: 16 kt, no barriers, no cp.async. 1-pass fp16.
#define AST  264                        // A k-stride elems (+8 pad)
#define BSTF 264                        // resident B k-stride elems (+8 pad)
#define A_OFF  0                        // 128*264*2 = 67584
#define B_OFF  67584                    // 256*264*2 = 135168
#define MISC   202752
// misc floats: hrow[512] b2s[256] relw[128] aggsm4[1024]
#define EDGE_SMEM (MISC + 1920*4)       // 210432

extern __shared__ __align__(16) char smem[];

__global__ __launch_bounds__(512, 1) void edge_kernel(
    const float* __restrict__ edges, const float* __restrict__ b2)
{
    const uint32_t sb = smem_u32(smem);
    float* hrow   = (float*)(smem + MISC);             // [512]
    float* b2s    = (float*)(smem + MISC + 512*4);     // [256]
    float* relw   = (float*)(smem + MISC + 768*4);     // [128]
    float* aggsm4 = (float*)(smem + MISC + 896*4);     // [4][256]

    const int tid = threadIdx.x;
    const int wid = tid >> 5, lid = tid & 31;
    const int wm  = wid & 3;             // rows wm*32 .. +32
    const int wn  = wid >> 2;            // cols wn*64 .. +64
    const int qr  = lid >> 2;
    const int qc  = (lid & 3) * 2;

    const int arow    = wm*32 + (lid & 15);
    const int acolsel = (lid & 16) ? 8 : 0;
    const int brow    = wn*64 + ((lid & 16) ? 8 : 0) + (lid & 7);
    const int bksel   = (lid & 8) ? 8 : 0;

    for (int k = 0; k < 2; k++) {
        __syncthreads();    // all readers of B (prev k) retired
        {   // ---- stage W2^T for this k: resident for all tiles
            const __half* w2 = g_w2t[k];
#pragma unroll
            for (int o = 0; o < 16; o++) {
                int opid = tid + o*512;          // 0..8191
                int nr = opid >> 5, part = opid & 31;
                cp16(sb + B_OFF + (uint32_t)(nr*BSTF + part*8)*2, w2 + nr*HH + part*8);
            }
            CP_COMMIT();
        }
        if (tid < 256) b2s[tid] = b2[k*HH + tid];
        CP_WAIT(0);
        __syncthreads();    // B + b2s visible

        for (int t = blockIdx.x; t < NTILE; t += GRID) {
            const int b  = t >> 5;
            const int g  = t & 31;
            const int n0 = 2*g, n1 = n0 + 1;

            __syncthreads();   // prev tile combine-write done; safe to overwrite
            hrow[tid] = g_Hr[k][((b<<6) + ((tid < 256) ? n0 : n1))*HH + (tid & 255)];
            if (tid < 128) {
                int recv = (tid < 64) ? n0 : n1, jl = tid & 63;
                relw[tid] = (jl < EPN) ? edges[((b*ETOT) + recv*EPN + jl)*2 + k] : 0.f;
            }
            aggsm4[tid]       = 0.f;
            aggsm4[tid + 512] = 0.f;
            __syncthreads();

            {   // ---- build A = relu(Hs[send]+Hr[recv]) -> fp16, rows 0..127
                int j = tid >> 2, q4 = tid & 3;
                int recv = (j < 64) ? n0 : n1;
                int jl = j & 63;
                int s = jl + (jl >= recv); if (s > 63) s = 63;   // pad row, relw=0
                const float* hs = &g_Hs[k][((b<<6) + s)*HH];
                const float* hr = &hrow[(j >= 64) ? 256 : 0];
                __half* ah = (__half*)(smem + A_OFF) + j*AST;
#pragma unroll 8
                for (int kk = q4*64; kk < q4*64 + 64; kk += 4) {
                    float4 v = *(const float4*)(hs + kk);
                    float r0 = fmaxf(v.x + hr[kk  ], 0.f);
                    float r1 = fmaxf(v.y + hr[kk+1], 0.f);
                    float r2 = fmaxf(v.z + hr[kk+2], 0.f);
                    float r3 = fmaxf(v.w + hr[kk+3], 0.f);
                    *(uint32_t*)(ah + kk)     = pack_h2(r0, r1);
                    *(uint32_t*)(ah + kk + 2) = pack_h2(r2, r3);
                }
            }
            __syncthreads();   // A visible

            float acc[2][8][4];
#pragma unroll
            for (int mt = 0; mt < 2; mt++)
#pragma unroll
                for (int nt = 0; nt < 8; nt++)
#pragma unroll
                    for (int r = 0; r < 4; r++) acc[mt][nt][r] = 0.f;

            // ---- mainloop: 16 kt, no barriers, B resident
#pragma unroll 4
            for (int kt = 0; kt < 16; kt++) {
                uint32_t aH[2][4];
#pragma unroll
                for (int mt = 0; mt < 2; mt++) {
                    uint32_t ao = (uint32_t)((arow + mt*16)*AST + kt*16 + acolsel)*2;
                    LDM_X4(aH[mt], sb + A_OFF + ao);
                }
                uint32_t bH[8][2];
#pragma unroll
                for (int p = 0; p < 4; p++) {
                    uint32_t bo = (uint32_t)((brow + p*16)*BSTF + kt*16 + bksel)*2;
                    uint32_t tt[4];
                    LDM_X4(tt, sb + B_OFF + bo);
                    bH[2*p][0] = tt[0];   bH[2*p][1] = tt[1];
                    bH[2*p+1][0] = tt[2]; bH[2*p+1][1] = tt[3];
                }
#pragma unroll
                for (int mt = 0; mt < 2; mt++)
#pragma unroll
                    for (int nt = 0; nt < 8; nt++)
                        mma16816(acc[mt][nt], aH[mt], bH[nt]);
            }

            // ---- epilogue: v = relu(D+b2)*relw, row-reduce, warp-exclusive banks
#pragma unroll
            for (int nt = 0; nt < 8; nt++) {
                int col0 = wn*64 + nt*8 + qc;
                float bb0 = b2s[col0], bb1 = b2s[col0 + 1];
                float v0 = 0.f, v1 = 0.f;
#pragma unroll
                for (int mt = 0; mt < 2; mt++) {
                    int r0 = wm*32 + mt*16 + qr;
                    float w0 = relw[r0], w1 = relw[r0 + 8];
                    v0 += w0*fmaxf(acc[mt][nt][0] + bb0, 0.f)
                        + w1*fmaxf(acc[mt][nt][2] + bb0, 0.f);
                    v1 += w0*fmaxf(acc[mt][nt][1] + bb1, 0.f)
                        + w1*fmaxf(acc[mt][nt][3] + bb1, 0.f);
                }
                v0 += __shfl_xor_sync(0xffffffffu, v0, 4);
                v0 += __shfl_xor_sync(0xffffffffu, v0, 8);
                v0 += __shfl_xor_sync(0xffffffffu, v0, 16);
                v1 += __shfl_xor_sync(0xffffffffu, v1, 4);
                v1 += __shfl_xor_sync(0xffffffffu, v1, 8);
                v1 += __shfl_xor_sync(0xffffffffu, v1, 16);
                if (lid < 4) {
                    aggsm4[wm*256 + col0    ] += v0;
                    aggsm4[wm*256 + col0 + 1] += v1;
                }
            }
            __syncthreads();   // banks complete

            {   // combine banks -> g_agg2[k]
                int recv = tid >> 8;       // 0 -> n0, 1 -> n1
                int col  = tid & 255;
                float v = aggsm4[(recv*2)*256 + col] + aggsm4[(recv*2 + 1)*256 + col];
                g_agg2[k][((b<<6) + (recv ? n1 : n0))*HH + col] = v;
            }
        }
    }
}

// ---------------------------------------------------------------- out-MLP on mma
#define BST 40
#define KC  32
#define OAST1 296
#define OAST2 264
#define H2ST  260
#define OA_HI 0
#define OA_LO 37888
#define OB_OFF 75776
#define OBBUF 20480
#define OMISC (OB_OFF + 3*OBBUF)        // 137216
#define OUT_SMEM (OMISC + 8256*4)       // 170240

__device__ __forceinline__ void stageB_o(const __half* w, int rowstride, int c, int buf,
                                         int tid, uint32_t sb) {
    uint32_t dst = sb + OB_OFF + buf*OBBUF;
#pragma unroll
    for (int o = 0; o < 4; o++) {
        int opid = tid + o*256;
        int n = opid >> 2, part = opid & 3;
        cp16(dst + (uint32_t)(n*BST + part*8)*2, w + n*rowstride + c*KC + part*8);
    }
}

__global__ __launch_bounds__(256, 1) void out_mma_kernel(
    const float* __restrict__ Wo3, const float* __restrict__ bo1,
    const float* __restrict__ bo2, const float* __restrict__ bo3,
    const float* __restrict__ Wq2, const float* __restrict__ bq2)
{
    const uint32_t sb = smem_u32(smem);
    float* bo1s = (float*)(smem + OMISC);
    float* bo2s = bo1s + 256;
    float* xres = bo2s + 256;
    float* wo3s = xres + 1536;
    float* bo3s = wo3s + 6144;
    float* wq2s = bo3s + 24;

    const int tid = threadIdx.x;
    const int wid = tid >> 5, lid = tid & 31;
    const int wm = wid & 1, wn = wid >> 1;
    const int qr = lid >> 2, qc = (lid & 3)*2;
    const int bn0 = blockIdx.x * 64;

    const int arow    = wm*32 + (lid & 15);
    const int acolsel = (lid & 16) ? 8 : 0;
    const int brow    = wn*64 + ((lid & 16) ? 8 : 0) + (lid & 7);
    const int bksel   = (lid & 8) ? 8 : 0;

    bo1s[tid] = bo1[tid];
    bo2s[tid] = bo2[tid];
    for (int i = tid; i < 6144; i += 256) wo3s[i] = Wo3[i];
    if (tid < 24) { bo3s[tid] = bo3[tid]; wq2s[tid] = Wq2[tid]; }

    stageB_o(g_w1t, 288, 0, 0, tid, sb); CP_COMMIT();

    {   // build aug A (hi/lo): rows 64, K 288 (280 + pad); agg = sum of k-partials
        int j = tid >> 2, q4 = tid & 3;
        __half* ah = (__half*)(smem + OA_HI) + j*OAST1;
        __half* al = (__half*)(smem + OA_LO) + j*OAST1;
        const float* xr = g_X + (bn0 + j)*DD;
        const float* a0 = g_agg2[0] + (bn0 + j)*HH;
        const float* a1 = g_agg2[1] + (bn0 + j)*HH;
#pragma unroll 4
        for (int kk = q4*72; kk < q4*72 + 72; kk += 2) {
            float v0 = (kk   < 24) ? xr[kk]   : ((kk   < 280) ? (a0[kk-24] + a1[kk-24]) : 0.f);
            float v1 = (kk+1 < 24) ? xr[kk+1] : ((kk+1 < 280) ? (a0[kk-23] + a1[kk-23]) : 0.f);
            __half h0 = __float2half_rn(v0), h1 = __float2half_rn(v1);
            *(uint32_t*)(ah + kk) = ((uint32_t)__half_as_ushort(h1) << 16) | __half_as_ushort(h0);
            *(uint32_t*)(al + kk) = pack_h2(v0 - __half2float(h0), v1 - __half2float(h1));
            if (kk < 24) { xres[j*24 + kk] = v0; xres[j*24 + kk + 1] = v1; }
        }
    }
    stageB_o(g_w1t, 288, 1, 1, tid, sb); CP_COMMIT();
    __syncthreads();

    float acc[2][8][4];
#pragma unroll
    for (int mt = 0; mt < 2; mt++)
#pragma unroll
        for (int nt = 0; nt < 8; nt++)
#pragma unroll
            for (int r = 0; r < 4; r++) acc[mt][nt][r] = 0.f;

    // ---- layer 1: K=288, 9 chunks
    for (int c = 0; c < 9; c++) {
        if (c < 8) CP_WAIT(1); else CP_WAIT(0);
        __syncthreads();
        const uint32_t Bh = sb + OB_OFF + (c % 3)*OBBUF;
#pragma unroll
        for (int kt = 0; kt < 2; kt++) {
            uint32_t aH[2][4], aL[2][4];
#pragma unroll
            for (int mt = 0; mt < 2; mt++) {
                uint32_t ao = (uint32_t)((arow + mt*16)*OAST1 + c*KC + kt*16 + acolsel)*2;
                LDM_X4(aH[mt], sb + OA_HI + ao);
                LDM_X4(aL[mt], sb + OA_LO + ao);
            }
            uint32_t bH[8][2];
#pragma unroll
            for (int p = 0; p < 4; p++) {
                uint32_t bo = (uint32_t)((brow + p*16)*BST + kt*16 + bksel)*2;
                uint32_t tt[4];
                LDM_X4(tt, Bh + bo);
                bH[2*p][0] = tt[0];   bH[2*p][1] = tt[1];
                bH[2*p+1][0] = tt[2]; bH[2*p+1][1] = tt[3];
            }
#pragma unroll
            for (int mt = 0; mt < 2; mt++)
#pragma unroll
                for (int nt = 0; nt < 8; nt++) {
                    mma16816(acc[mt][nt], aH[mt], bH[nt]);
                    mma16816(acc[mt][nt], aL[mt], bH[nt]);
                }
        }
        if (c < 7) { stageB_o(g_w1t, 288, c + 2, (c + 2) % 3, tid, sb); CP_COMMIT(); }
    }
    __syncthreads();

    stageB_o(g_w2o, 256, 0, 0, tid, sb); CP_COMMIT();
    stageB_o(g_w2o, 256, 1, 1, tid, sb); CP_COMMIT();

    {   // epilogue 1: h1 = relu(D + bo1) -> A region (hi/lo, stride OAST2)
        __half* ah = (__half*)(smem + OA_HI);
        __half* al = (__half*)(smem + OA_LO);
#pragma unroll
        for (int mt = 0; mt < 2; mt++)
#pragma unroll
            for (int nt = 0; nt < 8; nt++) {
                int row0 = wm*32 + mt*16 + qr;
                int col0 = wn*64 + nt*8 + qc;
                float b0 = bo1s[col0], b1 = bo1s[col0+1];
                float v0 = fmaxf(acc[mt][nt][0] + b0, 0.f);
                float v1 = fmaxf(acc[mt][nt][1] + b1, 0.f);
                float v2 = fmaxf(acc[mt][nt][2] + b0, 0.f);
                float v3 = fmaxf(acc[mt][nt][3] + b1, 0.f);
                __half h0 = __float2half_rn(v0), h1 = __float2half_rn(v1);
                __half h2v = __float2half_rn(v2), h3 = __float2half_rn(v3);
                *(uint32_t*)(ah + row0*OAST2 + col0) =
                    ((uint32_t)__half_as_ushort(h1) << 16) | __half_as_ushort(h0);
                *(uint32_t*)(ah + (row0+8)*OAST2 + col0) =
                    ((uint32_t)__half_as_ushort(h3) << 16) | __half_as_ushort(h2v);
                *(uint32_t*)(al + row0*OAST2 + col0) =
                    pack_h2(v0 - __half2float(h0), v1 - __half2float(h1));
                *(uint32_t*)(al + (row0+8)*OAST2 + col0) =
                    pack_h2(v2 - __half2float(h2v), v3 - __half2float(h3));
                acc[mt][nt][0] = acc[mt][nt][1] = acc[mt][nt][2] = acc[mt][nt][3] = 0.f;
            }
    }
    __syncthreads();

    // ---- layer 2: K=256, 8 chunks
    for (int c = 0; c < 8; c++) {
        if (c < 7) CP_WAIT(1); else CP_WAIT(0);
        __syncthreads();
        const uint32_t Bh = sb + OB_OFF + (c % 3)*OBBUF;
#pragma unroll
        for (int kt = 0; kt < 2; kt++) {
            uint32_t aH[2][4], aL[2][4];
#pragma unroll
            for (int mt = 0; mt < 2; mt++) {
                uint32_t ao = (uint32_t)((arow + mt*16)*OAST2 + c*KC + kt*16 + acolsel)*2;
                LDM_X4(aH[mt], sb + OA_HI + ao);
                LDM_X4(aL[mt], sb + OA_LO + ao);
            }
            uint32_t bH[8][2];
#pragma unroll
            for (int p = 0; p < 4; p++) {
                uint32_t bo = (uint32_t)((brow + p*16)*BST + kt*16 + bksel)*2;
                uint32_t tt[4];
                LDM_X4(tt, Bh + bo);
                bH[2*p][0] = tt[0];   bH[2*p][1] = tt[1];
                bH[2*p+1][0] = tt[2]; bH[2*p+1][1] = tt[3];
            }
#pragma unroll
            for (int mt = 0; mt < 2; mt++)
#pragma unroll
                for (int nt = 0; nt < 8; nt++) {
                    mma16816(acc[mt][nt], aH[mt], bH[nt]);
                    mma16816(acc[mt][nt], aL[mt], bH[nt]);
                }
        }
        if (c < 6) { stageB_o(g_w2o, 256, c + 2, (c + 2) % 3, tid, sb); CP_COMMIT(); }
    }
    __syncthreads();

    {   // epilogue 2: h2 = relu(D + bo2) -> fp32 smem
        float* h2f = (float*)(smem + OA_HI);
#pragma unroll
        for (int mt = 0; mt < 2; mt++)
#pragma unroll
            for (int nt = 0; nt < 8; nt++) {
                int row0 = wm*32 + mt*16 + qr;
                int col0 = wn*64 + nt*8 + qc;
                float b0 = bo2s[col0], b1 = bo2s[col0+1];
                float2 p0 = { fmaxf(acc[mt][nt][0] + b0, 0.f), fmaxf(acc[mt][nt][1] + b1, 0.f) };
                float2 p1 = { fmaxf(acc[mt][nt][2] + b0, 0.f), fmaxf(acc[mt][nt][3] + b1, 0.f) };
                *(float2*)(h2f + row0*H2ST + col0)     = p0;
                *(float2*)(h2f + (row0+8)*H2ST + col0) = p1;
            }
    }
    __syncthreads();

    {   // layer 3 + residual + q-head
        const float* h2f = (const float*)(smem + OA_HI);
        int rr = tid >> 2, cg = tid & 3;
        float s[6];
#pragma unroll
        for (int u = 0; u < 6; u++) s[u] = bo3s[cg*6 + u];
        const float* hrow_ = h2f + rr*H2ST;
#pragma unroll 4
        for (int i = 0; i < 256; i++) {
            float hv = hrow_[i];
            const float* wr = wo3s + i*24 + cg*6;
#pragma unroll
            for (int u = 0; u < 6; u++) s[u] = fmaf(hv, wr[u], s[u]);
        }
        float part = 0.f;
#pragma unroll
        for (int u = 0; u < 6; u++) {
            float pred = xres[rr*24 + cg*6 + u] + s[u];
            part = fmaf(pred, wq2s[cg*6 + u], part);
        }
        part += __shfl_xor_sync(0xffffffffu, part, 1);
        part += __shfl_xor_sync(0xffffffffu, part, 2);
        if (cg == 0) g_Q[bn0 + rr] = part + bq2[0];
    }
}

// ---------------------------------------------------------------- final dot
__global__ void q_kernel(const float* __restrict__ Wq3,
                         const float* __restrict__ bq3,
                         float* __restrict__ out)
{
    const int b = blockIdx.x;
    const int n = threadIdx.x;
    __shared__ float red[64];
    red[n] = g_Q[b*NN + n] * Wq3[n];
    __syncthreads();
    for (int off = 32; off > 0; off >>= 1) {
        if (n < off) red[n] += red[n + off];
        __syncthreads();
    }
    if (n == 0) out[b] = red[0] + bq3[0];
}

// ----------------------------------------------------------------
extern "C" void kernel_launch(void* const* d_in, const int* in_sizes, int n_in,
                              void* d_out, int out_size)
{
    const float* data  = (const float*)d_in[0];
    const float* act   = (const float*)d_in[1];
    const float* edges = (const float*)d_in[2];
    const float* W1  = (const float*)d_in[6];
    const float* b1  = (const float*)d_in[7];
    const float* W2  = (const float*)d_in[8];
    const float* b2  = (const float*)d_in[9];
    const float* Wo1 = (const float*)d_in[10];
    const float* bo1 = (const float*)d_in[11];
    const float* Wo2 = (const float*)d_in[12];
    const float* bo2 = (const float*)d_in[13];
    const float* Wo3 = (const float*)d_in[14];
    const float* bo3 = (const float*)d_in[15];
    const float* Wq2 = (const float*)d_in[16];
    const float* bq2 = (const float*)d_in[17];
    const float* Wq3 = (const float*)d_in[18];
    const float* bq3 = (const float*)d_in[19];
    float* out = (float*)d_out;

    wprep_kernel<<<512, 256>>>(W2);
    oprep_kernel<<<256, 256>>>(Wo1, Wo2);
    nodeproj_kernel<<<BB*NN, 256>>>(data, act, W1, b1);

    cudaFuncSetAttribute(edge_kernel, cudaFuncAttributeMaxDynamicSharedMemorySize,
                         EDGE_SMEM);
    edge_kernel<<<GRID, 512, EDGE_SMEM>>>(edges, b2);

    cudaFuncSetAttribute(out_mma_kernel, cudaFuncAttributeMaxDynamicSharedMemorySize,
                         OUT_SMEM);
    out_mma_kernel<<<BB*NN/64, 256, OUT_SMEM>>>(Wo3, bo1, bo2, bo3, Wq2, bq2);
    q_kernel<<<BB, 64>>>(Wq3, bq3, out);
}

// round 17
// speedup vs baseline: 1.5621x; 1.5621x over previous
#include <cuda_runtime.h>
#include <cuda_fp16.h>
#include <cstdint>

// ---------------------------------------------------------------- shapes
#define BB   64
#define NN   64
#define DD   24
#define HH   256
#define EPN  63
#define ETOT 4032
#define GRID 148
#define NTILE 2048

// ---------------------------------------------------------------- scratch
__device__ float g_X  [BB*NN*DD];
__device__ float g_Hs [2][BB*NN*HH];
__device__ float g_Hr [2][BB*NN*HH];
__device__ float g_agg2[2][BB*NN*HH];              // per-k partial aggregation
__device__ float g_Q  [BB*NN];
__device__ __align__(16) __half g_w2t[2][HH*HH];   // fp16(W2^T): [k][n][kk]
__device__ __align__(16) __half g_w1t[256*288];    // fp16(Wo1^T)
__device__ __align__(16) __half g_w2o[256*256];    // fp16(Wo2^T)

// ---------------------------------------------------------------- helpers
__device__ __forceinline__ void mma16816(float* c, const uint32_t* a, const uint32_t* b) {
    asm volatile(
        "mma.sync.aligned.m16n8k16.row.col.f32.f16.f16.f32 "
        "{%0,%1,%2,%3}, {%4,%5,%6,%7}, {%8,%9}, {%0,%1,%2,%3};\n"
        : "+f"(c[0]), "+f"(c[1]), "+f"(c[2]), "+f"(c[3])
        : "r"(a[0]), "r"(a[1]), "r"(a[2]), "r"(a[3]), "r"(b[0]), "r"(b[1]));
}
#define LDM_X4(r, addr) \
    asm volatile("ldmatrix.sync.aligned.m8n8.x4.shared.b16 {%0,%1,%2,%3}, [%4];" \
        : "=r"((r)[0]), "=r"((r)[1]), "=r"((r)[2]), "=r"((r)[3]) : "r"(addr))

__device__ __forceinline__ void cp16(uint32_t dst, const void* src) {
    asm volatile("cp.async.cg.shared.global [%0], [%1], 16;\n" :: "r"(dst), "l"(src) : "memory");
}
#define CP_COMMIT() asm volatile("cp.async.commit_group;\n" ::: "memory")
#define CP_WAIT(n)  asm volatile("cp.async.wait_group %0;\n" :: "n"(n) : "memory")

__device__ __forceinline__ uint32_t smem_u32(const void* p) {
    uint32_t a;
    asm("{ .reg .u64 t; cvta.to.shared.u64 t, %1; cvt.u32.u64 %0, t; }" : "=r"(a) : "l"(p));
    return a;
}
__device__ __forceinline__ uint32_t pack_h2(float x, float y) {
    __half hx = __float2half_rn(x), hy = __float2half_rn(y);
    return ((uint32_t)__half_as_ushort(hy) << 16) | __half_as_ushort(hx);
}

// ---------------------------------------------------------------- weight prep
__global__ __launch_bounds__(256) void wprep_kernel(const float* __restrict__ W2) {
    int k  = blockIdx.x >> 8;
    int c  = blockIdx.x & 255;
    int kk = threadIdx.x;
    g_w2t[k][c*HH + kk] = __float2half_rn(W2[(k*HH + kk)*HH + c]);
}
__global__ __launch_bounds__(256) void oprep_kernel(const float* __restrict__ Wo1,
                                                    const float* __restrict__ Wo2) {
    int n = blockIdx.x;
    int t = threadIdx.x;
    for (int kk = t; kk < 288; kk += 256)
        g_w1t[n*288 + kk] = (kk < 280) ? __float2half_rn(Wo1[kk*256 + n]) : __half(0.f);
    g_w2o[n*256 + t] = __float2half_rn(Wo2[t*256 + n]);
}

// ---------------------------------------------------------------- node projections
__global__ __launch_bounds__(256) void nodeproj_kernel(
    const float* __restrict__ data, const float* __restrict__ act,
    const float* __restrict__ W1, const float* __restrict__ b1)
{
    int bn = blockIdx.x;
    int h  = threadIdx.x;
    __shared__ float xs[DD];
    if (h < 16)      xs[h] = data[bn*32 + h];
    else if (h < 24) xs[h] = act [bn*16 + (h-16)];
    __syncthreads();
    if (h < DD) g_X[bn*DD + h] = xs[h];

    float xr[DD];
#pragma unroll
    for (int d = 0; d < DD; d++) xr[d] = xs[d];
#pragma unroll
    for (int k = 0; k < 2; k++) {
        float hs = 0.f, hr = b1[k*HH + h];
#pragma unroll
        for (int d = 0; d < DD; d++) {
            hs = fmaf(xr[d], W1[(k*48 +      d)*HH + h], hs);
            hr = fmaf(xr[d], W1[(k*48 + 24 + d)*HH + h], hr);
        }
        g_Hs[k][bn*HH + h] = hs;
        g_Hr[k][bn*HH + h] = hr;
    }
}

// ---------------------------------------------------------------- edge GEMM (persistent)
// grid=148, 512 threads (16 warps: wm=wid&3 rows, wn=wid>>2 cols).
// B resident per k; A-build: warp-per-8-rows, lane-per-4-cols (vector LDS/STS).
#define AST  264                        // A k-stride elems (+8 pad)
#define BSTF 264                        // resident B k-stride elems (+8 pad)
#define A_OFF  0                        // 128*264*2 = 67584
#define B_OFF  67584                    // 256*264*2 = 135168
#define MISC   202752
// misc floats: hrow[512] b2s[256] relw[128] aggsm4[1024]
#define EDGE_SMEM (MISC + 1920*4)       // 210432

extern __shared__ __align__(16) char smem[];

__global__ __launch_bounds__(512, 1) void edge_kernel(
    const float* __restrict__ edges, const float* __restrict__ b2)
{
    const uint32_t sb = smem_u32(smem);
    float* hrow   = (float*)(smem + MISC);             // [512]
    float* b2s    = (float*)(smem + MISC + 512*4);     // [256]
    float* relw   = (float*)(smem + MISC + 768*4);     // [128]
    float* aggsm4 = (float*)(smem + MISC + 896*4);     // [4][256]

    const int tid = threadIdx.x;
    const int wid = tid >> 5, lid = tid & 31;
    const int wm  = wid & 3;             // rows wm*32 .. +32
    const int wn  = wid >> 2;            // cols wn*64 .. +64
    const int qr  = lid >> 2;
    const int qc  = (lid & 3) * 2;

    const int arow    = wm*32 + (lid & 15);
    const int acolsel = (lid & 16) ? 8 : 0;
    const int brow    = wn*64 + ((lid & 16) ? 8 : 0) + (lid & 7);
    const int bksel   = (lid & 8) ? 8 : 0;

    for (int k = 0; k < 2; k++) {
        __syncthreads();    // all readers of B (prev k) retired
        {   // ---- stage W2^T for this k: resident for all tiles
            const __half* w2 = g_w2t[k];
#pragma unroll
            for (int o = 0; o < 16; o++) {
                int opid = tid + o*512;          // 0..8191
                int nr = opid >> 5, part = opid & 31;
                cp16(sb + B_OFF + (uint32_t)(nr*BSTF + part*8)*2, w2 + nr*HH + part*8);
            }
            CP_COMMIT();
        }
        if (tid < 256) b2s[tid] = b2[k*HH + tid];
        CP_WAIT(0);
        __syncthreads();    // B + b2s visible

        for (int t = blockIdx.x; t < NTILE; t += GRID) {
            const int b  = t >> 5;
            const int g  = t & 31;
            const int n0 = 2*g, n1 = n0 + 1;

            __syncthreads();   // prev tile combine-write done; safe to overwrite
            hrow[tid] = g_Hr[k][((b<<6) + ((tid < 256) ? n0 : n1))*HH + (tid & 255)];
            if (tid < 128) {
                int recv = (tid < 64) ? n0 : n1, jl = tid & 63;
                relw[tid] = (jl < EPN) ? edges[((b*ETOT) + recv*EPN + jl)*2 + k] : 0.f;
            }
            aggsm4[tid]       = 0.f;
            aggsm4[tid + 512] = 0.f;
            __syncthreads();

            {   // ---- build A: warp w handles rows 8w..8w+7, lane covers 4 cols x2
#pragma unroll
                for (int r = 0; r < 8; r++) {
                    int j = wid*8 + r;
                    int recv = (j < 64) ? n0 : n1;
                    int jl = j & 63;
                    int s = jl + (jl >= recv); if (s > 63) s = 63;   // pad, relw=0
                    const float* hs = &g_Hs[k][((b<<6) + s)*HH];
                    const float* hr = &hrow[(j >= 64) ? 256 : 0];
                    __half* ah = (__half*)(smem + A_OFF) + j*AST;
#pragma unroll
                    for (int h = 0; h < 2; h++) {
                        int kk = 4*lid + h*128;
                        float4 v = *(const float4*)(hs + kk);
                        float4 w = *(const float4*)(hr + kk);
                        uint2 pkd;
                        pkd.x = pack_h2(fmaxf(v.x + w.x, 0.f), fmaxf(v.y + w.y, 0.f));
                        pkd.y = pack_h2(fmaxf(v.z + w.z, 0.f), fmaxf(v.w + w.w, 0.f));
                        *(uint2*)(ah + kk) = pkd;
                    }
                }
            }
            __syncthreads();   // A visible

            float acc[2][8][4];
#pragma unroll
            for (int mt = 0; mt < 2; mt++)
#pragma unroll
                for (int nt = 0; nt < 8; nt++)
#pragma unroll
                    for (int r = 0; r < 4; r++) acc[mt][nt][r] = 0.f;

            // ---- mainloop: 16 kt, no barriers, B resident
#pragma unroll 4
            for (int kt = 0; kt < 16; kt++) {
                uint32_t aH[2][4];
#pragma unroll
                for (int mt = 0; mt < 2; mt++) {
                    uint32_t ao = (uint32_t)((arow + mt*16)*AST + kt*16 + acolsel)*2;
                    LDM_X4(aH[mt], sb + A_OFF + ao);
                }
                uint32_t bH[8][2];
#pragma unroll
                for (int p = 0; p < 4; p++) {
                    uint32_t bo = (uint32_t)((brow + p*16)*BSTF + kt*16 + bksel)*2;
                    uint32_t tt[4];
                    LDM_X4(tt, sb + B_OFF + bo);
                    bH[2*p][0] = tt[0];   bH[2*p][1] = tt[1];
                    bH[2*p+1][0] = tt[2]; bH[2*p+1][1] = tt[3];
                }
#pragma unroll
                for (int mt = 0; mt < 2; mt++)
#pragma unroll
                    for (int nt = 0; nt < 8; nt++)
                        mma16816(acc[mt][nt], aH[mt], bH[nt]);
            }

            // ---- epilogue: v = relu(D+b2)*relw, row-reduce, warp-exclusive banks
#pragma unroll
            for (int nt = 0; nt < 8; nt++) {
                int col0 = wn*64 + nt*8 + qc;
                float bb0 = b2s[col0], bb1 = b2s[col0 + 1];
                float v0 = 0.f, v1 = 0.f;
#pragma unroll
                for (int mt = 0; mt < 2; mt++) {
                    int r0 = wm*32 + mt*16 + qr;
                    float w0 = relw[r0], w1 = relw[r0 + 8];
                    v0 += w0*fmaxf(acc[mt][nt][0] + bb0, 0.f)
                        + w1*fmaxf(acc[mt][nt][2] + bb0, 0.f);
                    v1 += w0*fmaxf(acc[mt][nt][1] + bb1, 0.f)
                        + w1*fmaxf(acc[mt][nt][3] + bb1, 0.f);
                }
                v0 += __shfl_xor_sync(0xffffffffu, v0, 4);
                v0 += __shfl_xor_sync(0xffffffffu, v0, 8);
                v0 += __shfl_xor_sync(0xffffffffu, v0, 16);
                v1 += __shfl_xor_sync(0xffffffffu, v1, 4);
                v1 += __shfl_xor_sync(0xffffffffu, v1, 8);
                v1 += __shfl_xor_sync(0xffffffffu, v1, 16);
                if (lid < 4) {
                    aggsm4[wm*256 + col0    ] += v0;
                    aggsm4[wm*256 + col0 + 1] += v1;
                }
            }
            __syncthreads();   // banks complete

            {   // combine banks -> g_agg2[k]
                int recv = tid >> 8;       // 0 -> n0, 1 -> n1
                int col  = tid & 255;
                float v = aggsm4[(recv*2)*256 + col] + aggsm4[(recv*2 + 1)*256 + col];
                g_agg2[k][((b<<6) + (recv ? n1 : n0))*HH + col] = v;
            }
        }
    }
}

// ---------------------------------------------------------------- out-MLP on mma
#define BST 40
#define KC  32
#define OAST1 296
#define OAST2 264
#define H2ST  260
#define OA_HI 0
#define OA_LO 37888
#define OB_OFF 75776
#define OBBUF 20480
#define OMISC (OB_OFF + 3*OBBUF)        // 137216
#define OUT_SMEM (OMISC + 8256*4)       // 170240

__device__ __forceinline__ void stageB_o(const __half* w, int rowstride, int c, int buf,
                                         int tid, uint32_t sb) {
    uint32_t dst = sb + OB_OFF + buf*OBBUF;
#pragma unroll
    for (int o = 0; o < 4; o++) {
        int opid = tid + o*256;
        int n = opid >> 2, part = opid & 3;
        cp16(dst + (uint32_t)(n*BST + part*8)*2, w + n*rowstride + c*KC + part*8);
    }
}

__global__ __launch_bounds__(256, 1) void out_mma_kernel(
    const float* __restrict__ Wo3, const float* __restrict__ bo1,
    const float* __restrict__ bo2, const float* __restrict__ bo3,
    const float* __restrict__ Wq2, const float* __restrict__ bq2)
{
    const uint32_t sb = smem_u32(smem);
    float* bo1s = (float*)(smem + OMISC);
    float* bo2s = bo1s + 256;
    float* xres = bo2s + 256;
    float* wo3s = xres + 1536;
    float* bo3s = wo3s + 6144;
    float* wq2s = bo3s + 24;

    const int tid = threadIdx.x;
    const int wid = tid >> 5, lid = tid & 31;
    const int wm = wid & 1, wn = wid >> 1;
    const int qr = lid >> 2, qc = (lid & 3)*2;
    const int bn0 = blockIdx.x * 64;

    const int arow    = wm*32 + (lid & 15);
    const int acolsel = (lid & 16) ? 8 : 0;
    const int brow    = wn*64 + ((lid & 16) ? 8 : 0) + (lid & 7);
    const int bksel   = (lid & 8) ? 8 : 0;

    bo1s[tid] = bo1[tid];
    bo2s[tid] = bo2[tid];
    for (int i = tid; i < 6144; i += 256) wo3s[i] = Wo3[i];
    if (tid < 24) { bo3s[tid] = bo3[tid]; wq2s[tid] = Wq2[tid]; }

    stageB_o(g_w1t, 288, 0, 0, tid, sb); CP_COMMIT();

    {   // build aug A (hi/lo): rows 64, K 288 (280 + pad); agg = sum of k-partials
        int j = tid >> 2, q4 = tid & 3;
        __half* ah = (__half*)(smem + OA_HI) + j*OAST1;
        __half* al = (__half*)(smem + OA_LO) + j*OAST1;
        const float* xr = g_X + (bn0 + j)*DD;
        const float* a0 = g_agg2[0] + (bn0 + j)*HH;
        const float* a1 = g_agg2[1] + (bn0 + j)*HH;
#pragma unroll 4
        for (int kk = q4*72; kk < q4*72 + 72; kk += 2) {
            float v0 = (kk   < 24) ? xr[kk]   : ((kk   < 280) ? (a0[kk-24] + a1[kk-24]) : 0.f);
            float v1 = (kk+1 < 24) ? xr[kk+1] : ((kk+1 < 280) ? (a0[kk-23] + a1[kk-23]) : 0.f);
            __half h0 = __float2half_rn(v0), h1 = __float2half_rn(v1);
            *(uint32_t*)(ah + kk) = ((uint32_t)__half_as_ushort(h1) << 16) | __half_as_ushort(h0);
            *(uint32_t*)(al + kk) = pack_h2(v0 - __half2float(h0), v1 - __half2float(h1));
            if (kk < 24) { xres[j*24 + kk] = v0; xres[j*24 + kk + 1] = v1; }
        }
    }
    stageB_o(g_w1t, 288, 1, 1, tid, sb); CP_COMMIT();
    __syncthreads();

    float acc[2][8][4];
#pragma unroll
    for (int mt = 0; mt < 2; mt++)
#pragma unroll
        for (int nt = 0; nt < 8; nt++)
#pragma unroll
            for (int r = 0; r < 4; r++) acc[mt][nt][r] = 0.f;

    // ---- layer 1: K=288, 9 chunks
    for (int c = 0; c < 9; c++) {
        if (c < 8) CP_WAIT(1); else CP_WAIT(0);
        __syncthreads();
        const uint32_t Bh = sb + OB_OFF + (c % 3)*OBBUF;
#pragma unroll
        for (int kt = 0; kt < 2; kt++) {
            uint32_t aH[2][4], aL[2][4];
#pragma unroll
            for (int mt = 0; mt < 2; mt++) {
                uint32_t ao = (uint32_t)((arow + mt*16)*OAST1 + c*KC + kt*16 + acolsel)*2;
                LDM_X4(aH[mt], sb + OA_HI + ao);
                LDM_X4(aL[mt], sb + OA_LO + ao);
            }
            uint32_t bH[8][2];
#pragma unroll
            for (int p = 0; p < 4; p++) {
                uint32_t bo = (uint32_t)((brow + p*16)*BST + kt*16 + bksel)*2;
                uint32_t tt[4];
                LDM_X4(tt, Bh + bo);
                bH[2*p][0] = tt[0];   bH[2*p][1] = tt[1];
                bH[2*p+1][0] = tt[2]; bH[2*p+1][1] = tt[3];
            }
#pragma unroll
            for (int mt = 0; mt < 2; mt++)
#pragma unroll
                for (int nt = 0; nt < 8; nt++) {
                    mma16816(acc[mt][nt], aH[mt], bH[nt]);
                    mma16816(acc[mt][nt], aL[mt], bH[nt]);
                }
        }
        if (c < 7) { stageB_o(g_w1t, 288, c + 2, (c + 2) % 3, tid, sb); CP_COMMIT(); }
    }
    __syncthreads();

    stageB_o(g_w2o, 256, 0, 0, tid, sb); CP_COMMIT();
    stageB_o(g_w2o, 256, 1, 1, tid, sb); CP_COMMIT();

    {   // epilogue 1: h1 = relu(D + bo1) -> A region (hi/lo, stride OAST2)
        __half* ah = (__half*)(smem + OA_HI);
        __half* al = (__half*)(smem + OA_LO);
#pragma unroll
        for (int mt = 0; mt < 2; mt++)
#pragma unroll
            for (int nt = 0; nt < 8; nt++) {
                int row0 = wm*32 + mt*16 + qr;
                int col0 = wn*64 + nt*8 + qc;
                float b0 = bo1s[col0], b1 = bo1s[col0+1];
                float v0 = fmaxf(acc[mt][nt][0] + b0, 0.f);
                float v1 = fmaxf(acc[mt][nt][1] + b1, 0.f);
                float v2 = fmaxf(acc[mt][nt][2] + b0, 0.f);
                float v3 = fmaxf(acc[mt][nt][3] + b1, 0.f);
                __half h0 = __float2half_rn(v0), h1 = __float2half_rn(v1);
                __half h2v = __float2half_rn(v2), h3 = __float2half_rn(v3);
                *(uint32_t*)(ah + row0*OAST2 + col0) =
                    ((uint32_t)__half_as_ushort(h1) << 16) | __half_as_ushort(h0);
                *(uint32_t*)(ah + (row0+8)*OAST2 + col0) =
                    ((uint32_t)__half_as_ushort(h3) << 16) | __half_as_ushort(h2v);
                *(uint32_t*)(al + row0*OAST2 + col0) =
                    pack_h2(v0 - __half2float(h0), v1 - __half2float(h1));
                *(uint32_t*)(al + (row0+8)*OAST2 + col0) =
                    pack_h2(v2 - __half2float(h2v), v3 - __half2float(h3));
                acc[mt][nt][0] = acc[mt][nt][1] = acc[mt][nt][2] = acc[mt][nt][3] = 0.f;
            }
    }
    __syncthreads();

    // ---- layer 2: K=256, 8 chunks
    for (int c = 0; c < 8; c++) {
        if (c < 7) CP_WAIT(1); else CP_WAIT(0);
        __syncthreads();
        const uint32_t Bh = sb + OB_OFF + (c % 3)*OBBUF;
#pragma unroll
        for (int kt = 0; kt < 2; kt++) {
            uint32_t aH[2][4], aL[2][4];
#pragma unroll
            for (int mt = 0; mt < 2; mt++) {
                uint32_t ao = (uint32_t)((arow + mt*16)*OAST2 + c*KC + kt*16 + acolsel)*2;
                LDM_X4(aH[mt], sb + OA_HI + ao);
                LDM_X4(aL[mt], sb + OA_LO + ao);
            }
            uint32_t bH[8][2];
#pragma unroll
            for (int p = 0; p < 4; p++) {
                uint32_t bo = (uint32_t)((brow + p*16)*BST + kt*16 + bksel)*2;
                uint32_t tt[4];
                LDM_X4(tt, Bh + bo);
                bH[2*p][0] = tt[0];   bH[2*p][1] = tt[1];
                bH[2*p+1][0] = tt[2]; bH[2*p+1][1] = tt[3];
            }
#pragma unroll
            for (int mt = 0; mt < 2; mt++)
#pragma unroll
                for (int nt = 0; nt < 8; nt++) {
                    mma16816(acc[mt][nt], aH[mt], bH[nt]);
                    mma16816(acc[mt][nt], aL[mt], bH[nt]);
                }
        }
        if (c < 6) { stageB_o(g_w2o, 256, c + 2, (c + 2) % 3, tid, sb); CP_COMMIT(); }
    }
    __syncthreads();

    {   // epilogue 2: h2 = relu(D + bo2) -> fp32 smem
        float* h2f = (float*)(smem + OA_HI);
#pragma unroll
        for (int mt = 0; mt < 2; mt++)
#pragma unroll
            for (int nt = 0; nt < 8; nt++) {
                int row0 = wm*32 + mt*16 + qr;
                int col0 = wn*64 + nt*8 + qc;
                float b0 = bo2s[col0], b1 = bo2s[col0+1];
                float2 p0 = { fmaxf(acc[mt][nt][0] + b0, 0.f), fmaxf(acc[mt][nt][1] + b1, 0.f) };
                float2 p1 = { fmaxf(acc[mt][nt][2] + b0, 0.f), fmaxf(acc[mt][nt][3] + b1, 0.f) };
                *(float2*)(h2f + row0*H2ST + col0)     = p0;
                *(float2*)(h2f + (row0+8)*H2ST + col0) = p1;
            }
    }
    __syncthreads();

    {   // layer 3 + residual + q-head
        const float* h2f = (const float*)(smem + OA_HI);
        int rr = tid >> 2, cg = tid & 3;
        float s[6];
#pragma unroll
        for (int u = 0; u < 6; u++) s[u] = bo3s[cg*6 + u];
        const float* hrow_ = h2f + rr*H2ST;
#pragma unroll 4
        for (int i = 0; i < 256; i++) {
            float hv = hrow_[i];
            const float* wr = wo3s + i*24 + cg*6;
#pragma unroll
            for (int u = 0; u < 6; u++) s[u] = fmaf(hv, wr[u], s[u]);
        }
        float part = 0.f;
#pragma unroll
        for (int u = 0; u < 6; u++) {
            float pred = xres[rr*24 + cg*6 + u] + s[u];
            part = fmaf(pred, wq2s[cg*6 + u], part);
        }
        part += __shfl_xor_sync(0xffffffffu, part, 1);
        part += __shfl_xor_sync(0xffffffffu, part, 2);
        if (cg == 0) g_Q[bn0 + rr] = part + bq2[0];
    }
}

// ---------------------------------------------------------------- final dot
__global__ void q_kernel(const float* __restrict__ Wq3,
                         const float* __restrict__ bq3,
                         float* __restrict__ out)
{
    const int b = blockIdx.x;
    const int n = threadIdx.x;
    __shared__ float red[64];
    red[n] = g_Q[b*NN + n] * Wq3[n];
    __syncthreads();
    for (int off = 32; off > 0; off >>= 1) {
        if (n < off) red[n] += red[n + off];
        __syncthreads();
    }
    if (n == 0) out[b] = red[0] + bq3[0];
}

// ----------------------------------------------------------------
extern "C" void kernel_launch(void* const* d_in, const int* in_sizes, int n_in,
                              void* d_out, int out_size)
{
    const float* data  = (const float*)d_in[0];
    const float* act   = (const float*)d_in[1];
    const float* edges = (const float*)d_in[2];
    const float* W1  = (const float*)d_in[6];
    const float* b1  = (const float*)d_in[7];
    const float* W2  = (const float*)d_in[8];
    const float* b2  = (const float*)d_in[9];
    const float* Wo1 = (const float*)d_in[10];
    const float* bo1 = (const float*)d_in[11];
    const float* Wo2 = (const float*)d_in[12];
    const float* bo2 = (const float*)d_in[13];
    const float* Wo3 = (const float*)d_in[14];
    const float* bo3 = (const float*)d_in[15];
    const float* Wq2 = (const float*)d_in[16];
    const float* bq2 = (const float*)d_in[17];
    const float* Wq3 = (const float*)d_in[18];
    const float* bq3 = (const float*)d_in[19];
    float* out = (float*)d_out;

    wprep_kernel<<<512, 256>>>(W2);
    oprep_kernel<<<256, 256>>>(Wo1, Wo2);
    nodeproj_kernel<<<BB*NN, 256>>>(data, act, W1, b1);

    cudaFuncSetAttribute(edge_kernel, cudaFuncAttributeMaxDynamicSharedMemorySize,
                         EDGE_SMEM);
    edge_kernel<<<GRID, 512, EDGE_SMEM>>>(edges, b2);

    cudaFuncSetAttribute(out_mma_kernel, cudaFuncAttributeMaxDynamicSharedMemorySize,
                         OUT_SMEM);
    out_mma_kernel<<<BB*NN/64, 256, OUT_SMEM>>>(Wo3, bo1, bo2, bo3, Wq2, bq2);
    q_kernel<<<BB, 64>>>(Wq3, bq3, out);
}